// round 3
// baseline (speedup 1.0000x reference)
#include <cuda_runtime.h>

// VariantCoeLinear1d: 1D Rusanov FV solver, 128 rows x 2048 pts x 256 steps.
// One persistent CTA per row (128 CTAs, single wave). 256 threads x 8
// register-resident points.
//
// R3: halo exchange via warp shuffles (intra-warp) + tiny SMEM slots for the
// 7 warp edges only. All interface/update math hoisted BEFORE the single
// per-step barrier; post-barrier work is a 2-lane predicated fixup.
// Targets R2's L1-throughput (67%) + post-barrier serialization (issue 52.5%).

#define BATCH 128
#define NPTS  2048
#define STEPS 256
#define TPB   256
#define NW    (TPB / 32)
#define PPT   8   // TPB*PPT == NPTS

typedef unsigned long long u64;

static __device__ __forceinline__ u64 pk(float lo, float hi) {
    u64 r; asm("mov.b64 %0,{%1,%2};" : "=l"(r) : "f"(lo), "f"(hi)); return r;
}
static __device__ __forceinline__ void upk(float& lo, float& hi, u64 v) {
    asm("mov.b64 {%0,%1},%2;" : "=f"(lo), "=f"(hi) : "l"(v));
}
static __device__ __forceinline__ u64 f2fma(u64 a, u64 b, u64 c) {
    u64 d; asm("fma.rn.f32x2 %0,%1,%2,%3;" : "=l"(d) : "l"(a), "l"(b), "l"(c)); return d;
}
static __device__ __forceinline__ u64 f2mul(u64 a, u64 b) {
    u64 d; asm("mul.rn.f32x2 %0,%1,%2;" : "=l"(d) : "l"(a), "l"(b)); return d;
}

// Rusanov interface flux (without the 0.5, folded into HL):
// fh = (f_l + f_r) - max(a_l, a_r) * (u_r - u_l)
static __device__ __forceinline__ float iface(float ul, float fl, float al,
                                              float ur, float fr, float ar) {
    float am = fmaxf(al, ar);
    return fmaf(-am, ur - ul, fl + fr);
}

__global__ void __launch_bounds__(TPB, 1)
vcl_kernel(const float* __restrict__ init, float* __restrict__ out)
{
    // double-buffered warp-edge slots: {u, f, a, pad}
    __shared__ float4 sR[2][NW];  // lane 31 of warp w publishes its last point
    __shared__ float4 sL[2][NW];  // lane 0  of warp w publishes its first point

    const int row  = blockIdx.x;
    const int tid  = threadIdx.x;
    const int lane = tid & 31;
    const int wid  = tid >> 5;
    const int base = tid * PPT;
    const float HL = 0.5f * (float)(0.002 / (10.0 / 2048.0));  // 0.5*dt/dx

    // flux(u)  = B1 u + B2 u^2 + B3 u^3 + B4 u^4 + B6 u^6
    // flux'(u) = A0 + A1 u + A2 u^2 + A3 u^3 + A5 u^5     (c = beta/12)
    const u64 B1 = pk(1.5f, 1.5f);
    const u64 B2 = pk((float)(0.75 * 0.1 / 12.0),  (float)(0.75 * 0.1 / 12.0));
    const u64 B3 = pk((float)(-0.5 - 2.0 * 0.1 / 12.0), (float)(-0.5 - 2.0 * 0.1 / 12.0));
    const u64 B4 = pk((float)(1.5 * 0.1 / 12.0),   (float)(1.5 * 0.1 / 12.0));
    const u64 B6 = pk((float)(-0.25 * 0.1 / 12.0), (float)(-0.25 * 0.1 / 12.0));
    const u64 A0 = pk(1.5f, 1.5f);
    const u64 A1 = pk((float)(1.5 * 0.1 / 12.0),   (float)(1.5 * 0.1 / 12.0));
    const u64 A2 = pk((float)(-1.5 - 6.0 * 0.1 / 12.0), (float)(-1.5 - 6.0 * 0.1 / 12.0));
    const u64 A3 = pk((float)(6.0 * 0.1 / 12.0),   (float)(6.0 * 0.1 / 12.0));
    const u64 A5 = pk((float)(-1.5 * 0.1 / 12.0),  (float)(-1.5 * 0.1 / 12.0));
    const u64 ABSM = 0x7fffffff7fffffffULL;

    float u[PPT];
    {
        const float4* ip = reinterpret_cast<const float4*>(init + (size_t)row * NPTS + base);
        float4 a0 = ip[0], a1 = ip[1];
        u[0] = a0.x; u[1] = a0.y; u[2] = a0.z; u[3] = a0.w;
        u[4] = a1.x; u[5] = a1.y; u[6] = a1.z; u[7] = a1.w;
        float4* o0 = reinterpret_cast<float4*>(out + (size_t)row * NPTS + base);
        __stcs(o0, a0);
        __stcs(o0 + 1, a1);
    }

    float4* op = reinterpret_cast<float4*>(out + ((size_t)BATCH + row) * NPTS + base);
    const size_t ostride = (size_t)BATCH * NPTS / 4;

    int p = 0;
    #pragma unroll 1
    for (int s = 1; s < STEPS; ++s) {
        // ---- 1) flux + |flux'| for 8 owned points, packed 2-wide ----
        float f[PPT], a[PPT];
        #pragma unroll
        for (int i = 0; i < PPT / 2; ++i) {
            u64 U  = pk(u[2 * i], u[2 * i + 1]);
            u64 u2 = f2mul(U, U);
            u64 u3 = f2mul(u2, U);
            u64 u4 = f2mul(u2, u2);
            u64 u5 = f2mul(u2, u3);
            u64 u6 = f2mul(u3, u3);
            u64 F  = f2fma(B6, u6, f2fma(B4, u4, f2fma(B3, u3, f2fma(B2, u2, f2mul(B1, U)))));
            u64 P  = f2fma(A5, u5, f2fma(A3, u3, f2fma(A2, u2, f2fma(A1, U, A0))));
            u64 A  = P & ABSM;
            upk(f[2 * i], f[2 * i + 1], F);
            upk(a[2 * i], a[2 * i + 1], A);
        }

        // ---- 2) intra-warp halo via shuffles (no barrier needed) ----
        const unsigned FULL = 0xffffffffu;
        float um = __shfl_up_sync(FULL, u[PPT - 1], 1);
        float fm = __shfl_up_sync(FULL, f[PPT - 1], 1);
        float am = __shfl_up_sync(FULL, a[PPT - 1], 1);
        float up = __shfl_down_sync(FULL, u[0], 1);
        float fr = __shfl_down_sync(FULL, f[0], 1);
        float ar = __shfl_down_sync(FULL, a[0], 1);
        // (lane 0 / lane 31 get self-copies -> fixed up after the barrier)

        // ---- 3) all interfaces + all updates BEFORE the barrier ----
        float fh[PPT + 1];
        fh[0] = iface(um, fm, am, u[0], f[0], a[0]);
        #pragma unroll
        for (int i = 1; i < PPT; ++i)
            fh[i] = iface(u[i - 1], f[i - 1], a[i - 1], u[i], f[i], a[i]);
        fh[PPT] = iface(u[PPT - 1], f[PPT - 1], a[PPT - 1], up, fr, ar);

        float un[PPT];
        #pragma unroll
        for (int k = 0; k < PPT; ++k)
            un[k] = fmaf(-HL, fh[k + 1] - fh[k], u[k]);

        // ---- 4) warp-edge exchange: publish, barrier, 2-lane fixup ----
        if (lane == 31) sR[p][wid] = make_float4(u[PPT - 1], f[PPT - 1], a[PPT - 1], 0.0f);
        if (lane == 0)  sL[p][wid] = make_float4(u[0], f[0], a[0], 0.0f);
        __syncthreads();

        if (lane == 0 && wid > 0) {
            float4 e = sR[p][wid - 1];
            float fh0 = iface(e.x, e.y, e.z, u[0], f[0], a[0]);
            un[0] = fmaf(-HL, fh[1] - fh0, u[0]);
        }
        if (lane == 31 && wid < NW - 1) {
            float4 e = sL[p][wid + 1];
            float fhN = iface(u[PPT - 1], f[PPT - 1], a[PPT - 1], e.x, e.y, e.z);
            un[PPT - 1] = fmaf(-HL, fhN - fh[PPT - 1], u[PPT - 1]);
        }
        // outflow BC at global edges
        if (tid == 0)       un[0]       = un[1];
        if (tid == TPB - 1) un[PPT - 1] = un[PPT - 2];

        // ---- 5) stream frame (write-only; evict-first) ----
        __stcs(op,     make_float4(un[0], un[1], un[2], un[3]));
        __stcs(op + 1, make_float4(un[4], un[5], un[6], un[7]));
        op += ostride;

        #pragma unroll
        for (int k = 0; k < PPT; ++k) u[k] = un[k];
        p ^= 1;
    }
}

extern "C" void kernel_launch(void* const* d_in, const int* in_sizes, int n_in,
                              void* d_out, int out_size) {
    const float* init = (const float*)d_in[0];   // [128, 2048] fp32
    // d_in[1] = stepnum (int32) — fixed at 256 by the problem spec
    float* out = (float*)d_out;                  // [256, 128, 2048] fp32
    vcl_kernel<<<BATCH, TPB>>>(init, out);
}

// round 4
// speedup vs baseline: 1.4544x; 1.4544x over previous
#include <cuda_runtime.h>

// VariantCoeLinear1d: 1D Rusanov FV solver, 128 rows x 2048 pts x 256 steps.
// One CTA per row (128 CTAs, single wave). 256 threads x 8 register points.
//
// R4 (from R2, R3's shuffles reverted): u-ONLY halo exchange. Boundary un
// values are published to double-buffered SMEM at the END of each step; the
// next step opens with one __syncthreads, loads the 2 halo u's (scalar LDS,
// latency hidden behind the 4 owned f32x2 poly chains), and recomputes the
// neighbors' (f,|f'|) locally with one extra packed poly eval. No post-
// barrier fixups, 1 barrier/step, halo L1 traffic cut ~3x vs R2.

#define BATCH 128
#define NPTS  2048
#define STEPS 256
#define TPB   256
#define PPT   8   // TPB*PPT == NPTS

typedef unsigned long long u64;

static __device__ __forceinline__ u64 pk(float lo, float hi) {
    u64 r; asm("mov.b64 %0,{%1,%2};" : "=l"(r) : "f"(lo), "f"(hi)); return r;
}
static __device__ __forceinline__ void upk(float& lo, float& hi, u64 v) {
    asm("mov.b64 {%0,%1},%2;" : "=f"(lo), "=f"(hi) : "l"(v));
}
static __device__ __forceinline__ u64 f2fma(u64 a, u64 b, u64 c) {
    u64 d; asm("fma.rn.f32x2 %0,%1,%2,%3;" : "=l"(d) : "l"(a), "l"(b), "l"(c)); return d;
}
static __device__ __forceinline__ u64 f2mul(u64 a, u64 b) {
    u64 d; asm("mul.rn.f32x2 %0,%1,%2;" : "=l"(d) : "l"(a), "l"(b)); return d;
}

// fh = (f_l + f_r) - max(a_l,a_r) * (u_r - u_l)   (0.5 folded into HL)
static __device__ __forceinline__ float iface(float ul, float fl, float al,
                                              float ur, float fr, float ar) {
    float am = fmaxf(al, ar);
    return fmaf(-am, ur - ul, fl + fr);
}

__global__ void __launch_bounds__(TPB, 1)
vcl_kernel(const float* __restrict__ init, float* __restrict__ out)
{
    // double-buffered boundary-u slots
    __shared__ float sL[2][TPB];   // thread t's FIRST point
    __shared__ float sR[2][TPB];   // thread t's LAST point

    const int row  = blockIdx.x;
    const int tid  = threadIdx.x;
    const int base = tid * PPT;
    const int tl   = (tid > 0) ? tid - 1 : 0;          // clamped: edge dummies
    const int tr   = (tid < TPB - 1) ? tid + 1 : TPB - 1;  // overwritten by BC
    const float HL = 0.5f * (float)(0.002 / (10.0 / 2048.0));  // 0.5*dt/dx

    // flux(u)  = B1 u + B2 u^2 + B3 u^3 + B4 u^4 + B6 u^6
    // flux'(u) = A0 + A1 u + A2 u^2 + A3 u^3 + A5 u^5     (c = beta/12)
    const u64 B1 = pk(1.5f, 1.5f);
    const u64 B2 = pk((float)(0.75 * 0.1 / 12.0),  (float)(0.75 * 0.1 / 12.0));
    const u64 B3 = pk((float)(-0.5 - 2.0 * 0.1 / 12.0), (float)(-0.5 - 2.0 * 0.1 / 12.0));
    const u64 B4 = pk((float)(1.5 * 0.1 / 12.0),   (float)(1.5 * 0.1 / 12.0));
    const u64 B6 = pk((float)(-0.25 * 0.1 / 12.0), (float)(-0.25 * 0.1 / 12.0));
    const u64 A0 = pk(1.5f, 1.5f);
    const u64 A1 = pk((float)(1.5 * 0.1 / 12.0),   (float)(1.5 * 0.1 / 12.0));
    const u64 A2 = pk((float)(-1.5 - 6.0 * 0.1 / 12.0), (float)(-1.5 - 6.0 * 0.1 / 12.0));
    const u64 A3 = pk((float)(6.0 * 0.1 / 12.0),   (float)(6.0 * 0.1 / 12.0));
    const u64 A5 = pk((float)(-1.5 * 0.1 / 12.0),  (float)(-1.5 * 0.1 / 12.0));
    const u64 ABSM = 0x7fffffff7fffffffULL;

    float u[PPT];
    {
        const float4* ip = reinterpret_cast<const float4*>(init + (size_t)row * NPTS + base);
        float4 a0 = ip[0], a1 = ip[1];
        u[0] = a0.x; u[1] = a0.y; u[2] = a0.z; u[3] = a0.w;
        u[4] = a1.x; u[5] = a1.y; u[6] = a1.z; u[7] = a1.w;
        float4* o0 = reinterpret_cast<float4*>(out + (size_t)row * NPTS + base);
        __stcs(o0, a0);
        __stcs(o0 + 1, a1);
    }
    // publish initial boundaries into buffer 0
    sL[0][tid] = u[0];
    sR[0][tid] = u[PPT - 1];

    float4* op = reinterpret_cast<float4*>(out + ((size_t)BATCH + row) * NPTS + base);
    const size_t ostride = (size_t)BATCH * NPTS / 4;

    int p = 0;
    #pragma unroll 1
    for (int s = 1; s < STEPS; ++s) {
        __syncthreads();   // separates prev step's publishes from this step's reads

        // halo u loads issue first; 29-cyc LDS latency hidden behind owned polys
        float um = sR[p][tl];
        float up = sL[p][tr];

        // ---- flux + |flux'|: 4 owned packs + 1 halo pack (5 indep chains) ----
        float f[PPT], a[PPT];
        #pragma unroll
        for (int i = 0; i < PPT / 2; ++i) {
            u64 U  = pk(u[2 * i], u[2 * i + 1]);
            u64 u2 = f2mul(U, U);
            u64 u3 = f2mul(u2, U);
            u64 u4 = f2mul(u2, u2);
            u64 u5 = f2mul(u2, u3);
            u64 u6 = f2mul(u3, u3);
            u64 F  = f2fma(B6, u6, f2fma(B4, u4, f2fma(B3, u3, f2fma(B2, u2, f2mul(B1, U)))));
            u64 P  = f2fma(A5, u5, f2fma(A3, u3, f2fma(A2, u2, f2fma(A1, U, A0))));
            u64 A  = P & ABSM;
            upk(f[2 * i], f[2 * i + 1], F);
            upk(a[2 * i], a[2 * i + 1], A);
        }
        float fm, frr, am, arr;
        {
            u64 U  = pk(um, up);
            u64 u2 = f2mul(U, U);
            u64 u3 = f2mul(u2, U);
            u64 u4 = f2mul(u2, u2);
            u64 u5 = f2mul(u2, u3);
            u64 u6 = f2mul(u3, u3);
            u64 F  = f2fma(B6, u6, f2fma(B4, u4, f2fma(B3, u3, f2fma(B2, u2, f2mul(B1, U)))));
            u64 P  = f2fma(A5, u5, f2fma(A3, u3, f2fma(A2, u2, f2fma(A1, U, A0))));
            u64 A  = P & ABSM;
            upk(fm, frr, F);
            upk(am, arr, A);
        }

        // ---- interfaces fh[0..8] ----
        float fh[PPT + 1];
        fh[0] = iface(um, fm, am, u[0], f[0], a[0]);
        #pragma unroll
        for (int i = 1; i < PPT; ++i)
            fh[i] = iface(u[i - 1], f[i - 1], a[i - 1], u[i], f[i], a[i]);
        fh[PPT] = iface(u[PPT - 1], f[PPT - 1], a[PPT - 1], up, frr, arr);

        // ---- update + outflow BC ----
        float un[PPT];
        #pragma unroll
        for (int k = 0; k < PPT; ++k)
            un[k] = fmaf(-HL, fh[k + 1] - fh[k], u[k]);
        if (tid == 0)       un[0]       = un[1];
        if (tid == TPB - 1) un[PPT - 1] = un[PPT - 2];

        // ---- publish boundaries for next step (other buffer; no race) ----
        const int np = p ^ 1;
        sL[np][tid] = un[0];
        sR[np][tid] = un[PPT - 1];

        // ---- stream frame (write-only; evict-first) ----
        __stcs(op,     make_float4(un[0], un[1], un[2], un[3]));
        __stcs(op + 1, make_float4(un[4], un[5], un[6], un[7]));
        op += ostride;

        #pragma unroll
        for (int k = 0; k < PPT; ++k) u[k] = un[k];
        p = np;
    }
}

extern "C" void kernel_launch(void* const* d_in, const int* in_sizes, int n_in,
                              void* d_out, int out_size) {
    const float* init = (const float*)d_in[0];   // [128, 2048] fp32
    // d_in[1] = stepnum (int32) — fixed at 256 by the problem spec
    float* out = (float*)d_out;                  // [256, 128, 2048] fp32
    vcl_kernel<<<BATCH, TPB>>>(init, out);
}